// round 14
// baseline (speedup 1.0000x reference)
#include <cuda_runtime.h>
#include <math.h>

#define SQ 2048
#define EM 1024
#define DM 64
#define NH 16

// ---------------- scratch: packed bf16x2 hi/lo pair arrays ----------------
__device__ __align__(16) unsigned g_pKh[SQ * 32], g_pKl[SQ * 32];
__device__ __align__(16) unsigned g_pQh[SQ * 32], g_pQl[SQ * 32];
__device__ __align__(16) unsigned g_pVh[SQ * 32], g_pVl[SQ * 32];
__device__ __align__(16) unsigned g_hKh[NH * SQ * 32], g_hKl[NH * SQ * 32];
__device__ __align__(16) unsigned g_hQh[NH * SQ * 32], g_hQl[NH * SQ * 32];
__device__ __align__(16) unsigned g_tVh[NH * DM * (SQ / 2)], g_tVl[NH * DM * (SQ / 2)];
__device__ __align__(16) unsigned g_ch[SQ * (EM / 2)], g_cl[SQ * (EM / 2)];
__device__ __align__(16) unsigned g_Woh[EM * (EM / 2)], g_Wol[EM * (EM / 2)];
__device__ __align__(16) float    g_out[SQ * EM];

// ---------------- bf16 split helpers ----------------
__device__ __forceinline__ unsigned pk2(float x, float y) {
    unsigned r;
    asm("cvt.rn.bf16x2.f32 %0, %1, %2;" : "=r"(r) : "f"(y), "f"(x));
    return r;
}

__device__ __forceinline__ void sp2(float x, float y, unsigned& hi, unsigned& lo) {
    unsigned ux = __float_as_uint(x), uy = __float_as_uint(y);
    hi = __byte_perm(ux, uy, 0x7632);
    float rx = x - __uint_as_float(ux & 0xffff0000u);
    float ry = y - __uint_as_float(uy & 0xffff0000u);
    lo = pk2(rx, ry);
}

__device__ __forceinline__ void mma_bf16(float* d, const unsigned* a, const unsigned* b) {
    asm volatile(
        "mma.sync.aligned.m16n8k16.row.col.f32.bf16.bf16.f32 "
        "{%0,%1,%2,%3},{%4,%5,%6,%7},{%8,%9},{%0,%1,%2,%3};"
        : "+f"(d[0]), "+f"(d[1]), "+f"(d[2]), "+f"(d[3])
        : "r"(a[0]), "r"(a[1]), "r"(a[2]), "r"(a[3]), "r"(b[0]), "r"(b[1]));
}

__device__ __forceinline__ void cp16(unsigned* smem_dst, const void* gsrc) {
    unsigned daddr = (unsigned)__cvta_generic_to_shared(smem_dst);
    asm volatile("cp.async.cg.shared.global [%0], [%1], 16;" :: "r"(daddr), "l"(gsrc));
}

__device__ __forceinline__ void ldsm4(unsigned& r0, unsigned& r1, unsigned& r2, unsigned& r3,
                                      const unsigned* p) {
    unsigned addr = (unsigned)__cvta_generic_to_shared(p);
    asm volatile("ldmatrix.sync.aligned.m8n8.x4.shared.b16 {%0,%1,%2,%3}, [%4];"
                 : "=r"(r0), "=r"(r1), "=r"(r2), "=r"(r3) : "r"(addr));
}

// ======== split-bf16 3-term GEMM: C = A @ B^T (+bias), BK=32 ========
#define SK 20

template <int BM, int BN, int WM, int WN, bool ASPLIT, bool BSPLIT, bool OUTPAIR>
__device__ __forceinline__ void gemm3x(
    const float* A, const unsigned* Aph, const unsigned* Apl, int lda,
    const float* B, const unsigned* Bph, const unsigned* Bpl, int ldb,
    const float* bias,
    float* C, unsigned* Cph, unsigned* Cpl, int ldc,
    float oscale, int Kd, int m0, int n0,
    unsigned* Ah, unsigned* Al, unsigned* Bh, unsigned* Bl)
{
    constexpr int NT = WM * WN * 32;
    constexpr int MF = BM / (WM * 16);
    constexpr int NF = BN / (WN * 8);
    const int tid  = threadIdx.x;
    const int lane = tid & 31;
    const int warp = tid >> 5;
    const int wm   = warp % WM;
    const int wn   = warp / WM;
    const int g    = lane >> 2;
    const int lam  = lane & 3;

    float acc[MF][NF][4];
#pragma unroll
    for (int mf = 0; mf < MF; mf++)
#pragma unroll
        for (int nf = 0; nf < NF; nf++)
#pragma unroll
            for (int i = 0; i < 4; i++) acc[mf][nf][i] = 0.f;

    for (int k0 = 0; k0 < Kd; k0 += 32) {
        __syncthreads();
        if (ASPLIT) {
#pragma unroll
            for (int e = tid; e < BM * 4; e += NT) {
                int r = e >> 2, c = e & 3;
                size_t off = (size_t)(m0 + r) * lda + (k0 >> 1) + c * 4;
                *reinterpret_cast<uint4*>(Ah + r * SK + c * 4) = *reinterpret_cast<const uint4*>(Aph + off);
                *reinterpret_cast<uint4*>(Al + r * SK + c * 4) = *reinterpret_cast<const uint4*>(Apl + off);
            }
        } else {
#pragma unroll
            for (int e = tid; e < BM * 8; e += NT) {
                int r = e >> 3, c4 = e & 7;
                float4 v = *reinterpret_cast<const float4*>(A + (size_t)(m0 + r) * lda + k0 + c4 * 4);
                sp2(v.x, v.y, Ah[r * SK + c4 * 2 + 0], Al[r * SK + c4 * 2 + 0]);
                sp2(v.z, v.w, Ah[r * SK + c4 * 2 + 1], Al[r * SK + c4 * 2 + 1]);
            }
        }
        if (BSPLIT) {
#pragma unroll
            for (int e = tid; e < BN * 4; e += NT) {
                int r = e >> 2, c = e & 3;
                size_t off = (size_t)(n0 + r) * ldb + (k0 >> 1) + c * 4;
                *reinterpret_cast<uint4*>(Bh + r * SK + c * 4) = *reinterpret_cast<const uint4*>(Bph + off);
                *reinterpret_cast<uint4*>(Bl + r * SK + c * 4) = *reinterpret_cast<const uint4*>(Bpl + off);
            }
        } else {
#pragma unroll
            for (int e = tid; e < BN * 8; e += NT) {
                int r = e >> 3, c4 = e & 7;
                float4 v = *reinterpret_cast<const float4*>(B + (size_t)(n0 + r) * ldb + k0 + c4 * 4);
                sp2(v.x, v.y, Bh[r * SK + c4 * 2 + 0], Bl[r * SK + c4 * 2 + 0]);
                sp2(v.z, v.w, Bh[r * SK + c4 * 2 + 1], Bl[r * SK + c4 * 2 + 1]);
            }
        }
        __syncthreads();

#pragma unroll
        for (int kc = 0; kc < 2; kc++) {
            unsigned ah[MF][4], al[MF][4];
#pragma unroll
            for (int mf = 0; mf < MF; mf++) {
                const int r = wm * (MF * 16) + mf * 16 + g;
                ah[mf][0] = Ah[r * SK + kc * 8 + lam];
                ah[mf][1] = Ah[(r + 8) * SK + kc * 8 + lam];
                ah[mf][2] = Ah[r * SK + kc * 8 + lam + 4];
                ah[mf][3] = Ah[(r + 8) * SK + kc * 8 + lam + 4];
                al[mf][0] = Al[r * SK + kc * 8 + lam];
                al[mf][1] = Al[(r + 8) * SK + kc * 8 + lam];
                al[mf][2] = Al[r * SK + kc * 8 + lam + 4];
                al[mf][3] = Al[(r + 8) * SK + kc * 8 + lam + 4];
            }
#pragma unroll
            for (int nf = 0; nf < NF; nf++) {
                const int rb = wn * (NF * 8) + nf * 8 + g;
                unsigned bh[2], bl[2];
                bh[0] = Bh[rb * SK + kc * 8 + lam];
                bh[1] = Bh[rb * SK + kc * 8 + lam + 4];
                bl[0] = Bl[rb * SK + kc * 8 + lam];
                bl[1] = Bl[rb * SK + kc * 8 + lam + 4];
#pragma unroll
                for (int mf = 0; mf < MF; mf++) {
                    mma_bf16(acc[mf][nf], ah[mf], bl);
                    mma_bf16(acc[mf][nf], al[mf], bh);
                    mma_bf16(acc[mf][nf], ah[mf], bh);
                }
            }
        }
    }

#pragma unroll
    for (int mf = 0; mf < MF; mf++) {
        const int row = m0 + wm * (MF * 16) + mf * 16 + g;
#pragma unroll
        for (int nf = 0; nf < NF; nf++) {
            if (OUTPAIR) {
                const int pc = (n0 >> 1) + wn * (NF * 4) + nf * 4 + lam;
                float b0 = bias ? bias[2 * pc] : 0.f;
                float b1 = bias ? bias[2 * pc + 1] : 0.f;
                unsigned hi, lo;
                sp2((acc[mf][nf][0] + b0) * oscale, (acc[mf][nf][1] + b1) * oscale, hi, lo);
                Cph[(size_t)row * ldc + pc] = hi;
                Cpl[(size_t)row * ldc + pc] = lo;
                sp2((acc[mf][nf][2] + b0) * oscale, (acc[mf][nf][3] + b1) * oscale, hi, lo);
                Cph[(size_t)(row + 8) * ldc + pc] = hi;
                Cpl[(size_t)(row + 8) * ldc + pc] = lo;
            } else {
                const int col = n0 + wn * (NF * 8) + nf * 8 + 2 * lam;
                float b0 = bias ? bias[col] : 0.f;
                float b1 = bias ? bias[col + 1] : 0.f;
                float2 v0 = make_float2(acc[mf][nf][0] + b0, acc[mf][nf][1] + b1);
                float2 v1 = make_float2(acc[mf][nf][2] + b0, acc[mf][nf][3] + b1);
                *reinterpret_cast<float2*>(C + (size_t)row * ldc + col) = v0;
                *reinterpret_cast<float2*>(C + (size_t)(row + 8) * ldc + col) = v1;
            }
        }
    }
}

// ---------------- kernel 0: pre-split Wo ----------------
__global__ __launch_bounds__(128) void k_splitW(const float* __restrict__ Wo)
{
    const int r = blockIdx.x;
#pragma unroll
    for (int i = 0; i < 2; i++) {
        int c4 = threadIdx.x + i * 128;
        float4 v = *reinterpret_cast<const float4*>(Wo + (size_t)r * EM + c4 * 4);
        unsigned h0, l0, h1, l1;
        sp2(v.x, v.y, h0, l0);
        sp2(v.z, v.w, h1, l1);
        g_Woh[(size_t)r * 512 + c4 * 2 + 0] = h0;
        g_Wol[(size_t)r * 512 + c4 * 2 + 0] = l0;
        g_Woh[(size_t)r * 512 + c4 * 2 + 1] = h1;
        g_Wol[(size_t)r * 512 + c4 * 2 + 1] = l1;
    }
}

// ---------------- kernel 1: shared projections (BM=32 -> 192 CTAs) ----------------
__global__ __launch_bounds__(128) void k_proj(const float* __restrict__ x,
                                              const float* __restrict__ Wk,
                                              const float* __restrict__ Wq,
                                              const float* __restrict__ Wv)
{
    __shared__ unsigned Ah[32 * SK], Al[32 * SK], Bh[64 * SK], Bl[64 * SK];
    const float* W;
    unsigned *Ch, *Cl;
    if (blockIdx.z == 0)      { W = Wk; Ch = g_pKh; Cl = g_pKl; }
    else if (blockIdx.z == 1) { W = Wq; Ch = g_pQh; Cl = g_pQl; }
    else                      { W = Wv; Ch = g_pVh; Cl = g_pVl; }
    gemm3x<32, 64, 1, 4, false, false, true>(
        x, nullptr, nullptr, EM, W, nullptr, nullptr, EM, nullptr,
        nullptr, Ch, Cl, 32, 1.f, EM, blockIdx.y * 32, 0, Ah, Al, Bh, Bl);
}

// ----- kernel 2: per-head linears, single-shot K=64, LDSM; V path fuses transpose -----
#define HS 36

__global__ __launch_bounds__(128) void k_headlin(const float* __restrict__ hWk,
                                                 const float* __restrict__ hbk,
                                                 const float* __restrict__ hWv,
                                                 const float* __restrict__ hbv,
                                                 const float* __restrict__ hWq,
                                                 const float* __restrict__ hbq)
{
    __shared__ unsigned smbuf[4 * 64 * HS];
    unsigned* Ah = smbuf;
    unsigned* Al = smbuf + 64 * HS;
    unsigned* Bh = smbuf + 2 * 64 * HS;
    unsigned* Bl = smbuf + 3 * 64 * HS;

    const int z = blockIdx.z;
    const int t = z >> 4;
    const int h = z & 15;
    const int m0 = blockIdx.y * 64;
    const int tid  = threadIdx.x;
    const int lane = tid & 31;
    const int warp = tid >> 5;
    const int wm   = warp & 1;
    const int wn   = warp >> 1;
    const int g    = lane >> 2;
    const int lam  = lane & 3;

    const unsigned *Aph, *Apl;
    const float *B, *bias;
    float oscale = 1.f;
    if (t == 0)      { Aph = g_pKh; Apl = g_pKl; B = hWk + h * DM * DM; bias = hbk + h * DM; }
    else if (t == 2) { Aph = g_pQh; Apl = g_pQl; B = hWq + h * DM * DM; bias = hbq + h * DM; oscale = 0.125f; }
    else             { Aph = g_pVh; Apl = g_pVl; B = hWv + h * DM * DM; bias = hbv + h * DM; }

#pragma unroll
    for (int i = 0; i < 4; i++) {
        int e = tid + i * 128;
        int r = e >> 3, c = e & 7;
        size_t off = (size_t)(m0 + r) * 32 + c * 4;
        *reinterpret_cast<uint4*>(Ah + r * HS + c * 4) = *reinterpret_cast<const uint4*>(Aph + off);
        *reinterpret_cast<uint4*>(Al + r * HS + c * 4) = *reinterpret_cast<const uint4*>(Apl + off);
    }
#pragma unroll
    for (int i = 0; i < 8; i++) {
        int e = tid + i * 128;
        int r = e >> 4, c4 = e & 15;
        float4 v = *reinterpret_cast<const float4*>(B + (size_t)r * DM + c4 * 4);
        sp2(v.x, v.y, Bh[r * HS + c4 * 2 + 0], Bl[r * HS + c4 * 2 + 0]);
        sp2(v.z, v.w, Bh[r * HS + c4 * 2 + 1], Bl[r * HS + c4 * 2 + 1]);
    }
    __syncthreads();

    const int lrowA = ((lane >> 3) & 1) * 8 + (lane & 7);
    const int lcolA = (lane >> 4) * 4;
    const int quad  = lane >> 3;
    const int lrowB = (quad >> 1) * 8 + (lane & 7);
    const int lcolB = (quad & 1) * 4;

    float acc[2][4][4];
#pragma unroll
    for (int mf = 0; mf < 2; mf++)
#pragma unroll
        for (int nf = 0; nf < 4; nf++)
#pragma unroll
            for (int i = 0; i < 4; i++) acc[mf][nf][i] = 0.f;

#pragma unroll
    for (int kc = 0; kc < 4; kc++) {
        unsigned ah[2][4], al[2][4];
#pragma unroll
        for (int mf = 0; mf < 2; mf++) {
            const int idx = (wm * 32 + mf * 16 + lrowA) * HS + kc * 8 + lcolA;
            ldsm4(ah[mf][0], ah[mf][1], ah[mf][2], ah[mf][3], Ah + idx);
            ldsm4(al[mf][0], al[mf][1], al[mf][2], al[mf][3], Al + idx);
        }
#pragma unroll
        for (int nf2 = 0; nf2 < 2; nf2++) {
            const int idx = (wn * 32 + nf2 * 16 + lrowB) * HS + kc * 8 + lcolB;
            unsigned h0, h1, h2, h3, lo0, lo1, lo2, lo3;
            ldsm4(h0, h1, h2, h3, Bh + idx);
            ldsm4(lo0, lo1, lo2, lo3, Bl + idx);
            unsigned bh[2], bl[2];
            bh[0] = h0;  bh[1] = h1;  bl[0] = lo0; bl[1] = lo1;
#pragma unroll
            for (int mf = 0; mf < 2; mf++) {
                mma_bf16(acc[mf][2 * nf2], ah[mf], bl);
                mma_bf16(acc[mf][2 * nf2], al[mf], bh);
                mma_bf16(acc[mf][2 * nf2], ah[mf], bh);
            }
            bh[0] = h2;  bh[1] = h3;  bl[0] = lo2; bl[1] = lo3;
#pragma unroll
            for (int mf = 0; mf < 2; mf++) {
                mma_bf16(acc[mf][2 * nf2 + 1], ah[mf], bl);
                mma_bf16(acc[mf][2 * nf2 + 1], al[mf], bh);
                mma_bf16(acc[mf][2 * nf2 + 1], ah[mf], bh);
            }
        }
    }

    if (t == 1) {
        // fused transpose: stage f32 tile in smem (overlaid on dead Ah/Al), then
        // split adjacent-s pairs into g_tVh/g_tVl (bit-identical to old k_transpose).
        __syncthreads();
        float* tv = reinterpret_cast<float*>(smbuf);   // 64 x 65 floats
#pragma unroll
        for (int mf = 0; mf < 2; mf++) {
            const int r = wm * 32 + mf * 16 + g;       // local s row
#pragma unroll
            for (int nf = 0; nf < 4; nf++) {
                const int c = wn * 32 + nf * 8 + 2 * lam;
                tv[r * 65 + c]           = acc[mf][nf][0] + bias[c];
                tv[r * 65 + c + 1]       = acc[mf][nf][1] + bias[c + 1];
                tv[(r + 8) * 65 + c]     = acc[mf][nf][2] + bias[c];
                tv[(r + 8) * 65 + c + 1] = acc[mf][nf][3] + bias[c + 1];
            }
        }
        __syncthreads();
#pragma unroll
        for (int i = 0; i < 16; i++) {
            int o = tid + i * 128;       // 2048 outputs
            int d = o >> 5, p = o & 31;
            unsigned hi, lo;
            sp2(tv[(2 * p) * 65 + d], tv[(2 * p + 1) * 65 + d], hi, lo);
            size_t idx = ((size_t)h * DM + d) * (SQ / 2) + (m0 >> 1) + p;
            g_tVh[idx] = hi;
            g_tVl[idx] = lo;
        }
    } else {
        unsigned* Cph = (t == 0) ? g_hKh + (size_t)h * SQ * 32 : g_hQh + (size_t)h * SQ * 32;
        unsigned* Cpl = (t == 0) ? g_hKl + (size_t)h * SQ * 32 : g_hQl + (size_t)h * SQ * 32;
#pragma unroll
        for (int mf = 0; mf < 2; mf++) {
            const int row = m0 + wm * 32 + mf * 16 + g;
#pragma unroll
            for (int nf = 0; nf < 4; nf++) {
                const int pc = wn * 16 + nf * 4 + lam;
                float b0 = bias[2 * pc], b1 = bias[2 * pc + 1];
                unsigned hi, lo;
                sp2((acc[mf][nf][0] + b0) * oscale, (acc[mf][nf][1] + b1) * oscale, hi, lo);
                Cph[(size_t)row * 32 + pc] = hi;
                Cpl[(size_t)row * 32 + pc] = lo;
                sp2((acc[mf][nf][2] + b0) * oscale, (acc[mf][nf][3] + b1) * oscale, hi, lo);
                Cph[(size_t)(row + 8) * 32 + pc] = hi;
                Cpl[(size_t)(row + 8) * 32 + pc] = lo;
            }
        }
    }
}

// -- kernel 3: flash attention, 256 thr / 128 q-rows, cp.async 3-stage, LDSM frags --
#define AS 36
#define TW (64 * AS)
#define STAGE_W (4 * TW)
#define NIT (SQ / 64)

__global__ __launch_bounds__(256, 1) void k_attn()
{
    extern __shared__ unsigned sm[];
    const int h    = blockIdx.y;
    const int tid  = threadIdx.x;
    const int lane = tid & 31;
    const int warp = tid >> 5;
    const int g    = lane >> 2;
    const int lam  = lane & 3;
    const int q0   = blockIdx.x * 128 + warp * 16;

    const int quad = lane >> 3;
    const int lr   = lane & 7;
    const int lrow = (quad >> 1) * 8 + lr;
    const int lcol = (quad & 1) * 4;

    const unsigned* Qh_ = g_hQh + (size_t)h * SQ * 32;
    const unsigned* Ql_ = g_hQl + (size_t)h * SQ * 32;
    const unsigned* Kh_ = g_hKh + (size_t)h * SQ * 32;
    const unsigned* Kl_ = g_hKl + (size_t)h * SQ * 32;
    const unsigned* Vh_ = g_tVh + (size_t)h * DM * (SQ / 2);
    const unsigned* Vl_ = g_tVl + (size_t)h * DM * (SQ / 2);

    unsigned qh[4][4], ql[4][4];
#pragma unroll
    for (int kc = 0; kc < 4; kc++) {
        qh[kc][0] = Qh_[(size_t)(q0 + g) * 32 + kc * 8 + lam];
        qh[kc][1] = Qh_[(size_t)(q0 + g + 8) * 32 + kc * 8 + lam];
        qh[kc][2] = Qh_[(size_t)(q0 + g) * 32 + kc * 8 + 4 + lam];
        qh[kc][3] = Qh_[(size_t)(q0 + g + 8) * 32 + kc * 8 + 4 + lam];
        ql[kc][0] = Ql_[(size_t)(q0 + g) * 32 + kc * 8 + lam];
        ql[kc][1] = Ql_[(size_t)(q0 + g + 8) * 32 + kc * 8 + lam];
        ql[kc][2] = Ql_[(size_t)(q0 + g) * 32 + kc * 8 + 4 + lam];
        ql[kc][3] = Ql_[(size_t)(q0 + g + 8) * 32 + kc * 8 + 4 + lam];
    }

    float o[8][4];
#pragma unroll
    for (int nf = 0; nf < 8; nf++)
#pragma unroll
        for (int i = 0; i < 4; i++) o[nf][i] = 0.f;
    float m0r = -1e30f, m1r = -1e30f, l0 = 0.f, l1 = 0.f;

    auto fill = [&](int stage, int t0) {
        unsigned* bKh = sm + stage * STAGE_W;
        unsigned* bKl = bKh + TW;
        unsigned* bVh = bKl + TW;
        unsigned* bVl = bVh + TW;
#pragma unroll
        for (int i = 0; i < 2; i++) {
            int e = tid + i * 256;
            int r = e >> 3, c = e & 7;
            size_t ko = (size_t)(t0 + r) * 32 + c * 4;
            cp16(bKh + r * AS + c * 4, Kh_ + ko);
            cp16(bKl + r * AS + c * 4, Kl_ + ko);
            size_t vo = (size_t)r * (SQ / 2) + (t0 >> 1) + c * 4;
            cp16(bVh + r * AS + c * 4, Vh_ + vo);
            cp16(bVl + r * AS + c * 4, Vl_ + vo);
        }
        asm volatile("cp.async.commit_group;");
    };

    fill(0, 0);
    fill(1, 64);

    for (int it = 0; it < NIT; it++) {
        const int cur = it % 3;
        if (it + 2 < NIT) {
            fill((it + 2) % 3, (it + 2) * 64);
            asm volatile("cp.async.wait_group 2;");
        } else if (it + 1 < NIT) {
            asm volatile("cp.async.wait_group 1;");
        } else {
            asm volatile("cp.async.wait_group 0;");
        }
        __syncthreads();

        const unsigned* sKh = sm + cur * STAGE_W;
        const unsigned* sKl = sKh + TW;
        const unsigned* sVh = sKl + TW;
        const unsigned* sVl = sVh + TW;

        float s[8][4];
#pragma unroll
        for (int nf = 0; nf < 8; nf++)
            s[nf][0] = s[nf][1] = s[nf][2] = s[nf][3] = 0.f;
#pragma unroll
        for (int kc = 0; kc < 4; kc++) {
#pragma unroll
            for (int nf2 = 0; nf2 < 4; nf2++) {
                const int idx = (nf2 * 16 + lrow) * AS + kc * 8 + lcol;
                unsigned h0, h1, h2, h3, lo0, lo1, lo2, lo3;
                ldsm4(h0, h1, h2, h3, sKh + idx);
                ldsm4(lo0, lo1, lo2, lo3, sKl + idx);
                unsigned bh[2], bl[2];
                bh[0] = h0;  bh[1] = h1;  bl[0] = lo0; bl[1] = lo1;
                mma_bf16(s[2 * nf2], qh[kc], bl);
                mma_bf16(s[2 * nf2], ql[kc], bh);
                mma_bf16(s[2 * nf2], qh[kc], bh);
                bh[0] = h2;  bh[1] = h3;  bl[0] = lo2; bl[1] = lo3;
                mma_bf16(s[2 * nf2 + 1], qh[kc], bl);
                mma_bf16(s[2 * nf2 + 1], ql[kc], bh);
                mma_bf16(s[2 * nf2 + 1], qh[kc], bh);
            }
        }

        float mx0 = m0r, mx1 = m1r;
#pragma unroll
        for (int nf = 0; nf < 8; nf++) {
            mx0 = fmaxf(mx0, fmaxf(s[nf][0], s[nf][1]));
            mx1 = fmaxf(mx1, fmaxf(s[nf][2], s[nf][3]));
        }
        mx0 = fmaxf(mx0, __shfl_xor_sync(0xffffffffu, mx0, 1));
        mx0 = fmaxf(mx0, __shfl_xor_sync(0xffffffffu, mx0, 2));
        mx1 = fmaxf(mx1, __shfl_xor_sync(0xffffffffu, mx1, 1));
        mx1 = fmaxf(mx1, __shfl_xor_sync(0xffffffffu, mx1, 2));

        const float c0 = __expf(m0r - mx0);
        const float c1 = __expf(m1r - mx1);
        m0r = mx0; m1r = mx1;

        float ls0 = 0.f, ls1 = 0.f;
#pragma unroll
        for (int nf = 0; nf < 8; nf++) {
            s[nf][0] = __expf(s[nf][0] - mx0);
            s[nf][1] = __expf(s[nf][1] - mx0);
            s[nf][2] = __expf(s[nf][2] - mx1);
            s[nf][3] = __expf(s[nf][3] - mx1);
            ls0 += s[nf][0] + s[nf][1];
            ls1 += s[nf][2] + s[nf][3];
        }
        ls0 += __shfl_xor_sync(0xffffffffu, ls0, 1);
        ls0 += __shfl_xor_sync(0xffffffffu, ls0, 2);
        ls1 += __shfl_xor_sync(0xffffffffu, ls1, 1);
        ls1 += __shfl_xor_sync(0xffffffffu, ls1, 2);
        l0 = l0 * c0 + ls0;
        l1 = l1 * c1 + ls1;
#pragma unroll
        for (int nf = 0; nf < 8; nf++) {
            o[nf][0] *= c0; o[nf][1] *= c0;
            o[nf][2] *= c1; o[nf][3] *= c1;
        }

        unsigned ph[4][4], pl[4][4];
#pragma unroll
        for (int kc = 0; kc < 4; kc++) {
            sp2(s[2 * kc][0],     s[2 * kc][1],     ph[kc][0], pl[kc][0]);
            sp2(s[2 * kc][2],     s[2 * kc][3],     ph[kc][1], pl[kc][1]);
            sp2(s[2 * kc + 1][0], s[2 * kc + 1][1], ph[kc][2], pl[kc][2]);
            sp2(s[2 * kc + 1][2], s[2 * kc + 1][3], ph[kc][3], pl[kc][3]);
        }

#pragma unroll
        for (int kc = 0; kc < 4; kc++) {
#pragma unroll
            for (int nf2 = 0; nf2 < 4; nf2++) {
                const int idx = (nf2 * 16 + lrow) * AS + kc * 8 + lcol;
                unsigned h0, h1, h2, h3, lo0, lo1, lo2, lo3;
                ldsm4(h0, h1, h2, h3, sVh + idx);
                ldsm4(lo0, lo1, lo2, lo3, sVl + idx);
                unsigned bh[2], bl[2];
                bh[0] = h0;  bh[1] = h1;  bl[0] = lo0; bl[1] = lo1;
                mma_bf16(o[2 * nf2], ph[kc], bl);
                mma_bf16(o[2 * nf2], pl[kc], bh);
                mma_bf16(o[2 * nf2], ph[kc], bh);
                bh[0] = h2;  bh[1] = h3;  bl[0] = lo2; bl[1] = lo3;
                mma_bf16(o[2 * nf2 + 1], ph[kc], bl);
                mma_bf16(o[2 * nf2 + 1], pl[kc], bh);
                mma_bf16(o[2 * nf2 + 1], ph[kc], bh);
            }
        }
        __syncthreads();
    }

    const float inv0 = 1.f / l0;
    const float inv1 = 1.f / l1;
#pragma unroll
    for (int nf = 0; nf < 8; nf++) {
        const int pc = h * 32 + nf * 4 + lam;
        unsigned hi, lo;
        sp2(o[nf][0] * inv0, o[nf][1] * inv0, hi, lo);
        g_ch[(size_t)(q0 + g) * 512 + pc] = hi;
        g_cl[(size_t)(q0 + g) * 512 + pc] = lo;
        sp2(o[nf][2] * inv1, o[nf][3] * inv1, hi, lo);
        g_ch[(size_t)(q0 + g + 8) * 512 + pc] = hi;
        g_cl[(size_t)(q0 + g + 8) * 512 + pc] = lo;
    }
}

// ---------- kernel 4: out-proj, cp.async 2-stage pipelined, LDSM frags ----------
#define OS 20
#define OTW (128 * OS)
#define OSTAGE (4 * OTW)

__global__ __launch_bounds__(256) void k_outproj(const float* __restrict__ bo)
{
    extern __shared__ unsigned sm[];
    const int tid  = threadIdx.x;
    const int lane = tid & 31;
    const int warp = tid >> 5;
    const int wm   = warp % 4;
    const int wn   = warp / 4;
    const int g    = lane >> 2;
    const int lam  = lane & 3;
    const int m0   = blockIdx.y * 128;
    const int n0   = blockIdx.x * 128;

    const int lrowA = ((lane >> 3) & 1) * 8 + (lane & 7);
    const int lcolA = (lane >> 4) * 4;
    const int quad  = lane >> 3;
    const int lrowB = (quad >> 1) * 8 + (lane & 7);
    const int lcolB = (quad & 1) * 4;

    float acc[2][8][4];
#pragma unroll
    for (int mf = 0; mf < 2; mf++)
#pragma unroll
        for (int nf = 0; nf < 8; nf++)
#pragma unroll
            for (int i = 0; i < 4; i++) acc[mf][nf][i] = 0.f;

    auto fill = [&](int stage, int k0) {
        unsigned* Ah = sm + stage * OSTAGE;
        unsigned* Al = Ah + OTW;
        unsigned* Bh = Al + OTW;
        unsigned* Bl = Bh + OTW;
#pragma unroll
        for (int i = 0; i < 2; i++) {
            int e = tid + i * 256;
            int r = e >> 2, c = e & 3;
            size_t ao = (size_t)(m0 + r) * 512 + (k0 >> 1) + c * 4;
            cp16(Ah + r * OS + c * 4, g_ch + ao);
            cp16(Al + r * OS + c * 4, g_cl + ao);
            size_t bo_ = (size_t)(n0 + r) * 512 + (k0 >> 1) + c * 4;
            cp16(Bh + r * OS + c * 4, g_Woh + bo_);
            cp16(Bl + r * OS + c * 4, g_Wol + bo_);
        }
        asm volatile("cp.async.commit_group;");
    };

    fill(0, 0);

    for (int it = 0; it < EM / 32; it++) {
        const int cur = it & 1;
        if (it + 1 < EM / 32) {
            fill(cur ^ 1, (it + 1) * 32);
            asm volatile("cp.async.wait_group 1;");
        } else {
            asm volatile("cp.async.wait_group 0;");
        }
        __syncthreads();

        const unsigned* Ah = sm + cur * OSTAGE;
        const unsigned* Al = Ah + OTW;
        const unsigned* Bh = Al + OTW;
        const unsigned* Bl = Bh + OTW;

#pragma unroll
        for (int kc = 0; kc < 2; kc++) {
            unsigned ah[2][4], al[2][4];
#pragma unroll
            for (int mf = 0; mf < 2; mf++) {
                const int idx = (wm * 32 + mf * 16 + lrowA) * OS + kc * 8 + lcolA;
                ldsm4(ah[mf][0], ah[mf][1], ah[mf][2], ah[mf][3], Ah + idx);
                ldsm4(al[mf][0], al[mf][1], al[mf][2], al[mf][3], Al + idx);
            }
#pragma unroll
            for (int nf2 = 0; nf2 < 4; nf2++) {
                const int idx = (wn * 64 + nf2 * 16 + lrowB) * OS + kc * 8 + lcolB;
                unsigned h0, h1, h2, h3, lo0, lo1, lo2, lo3;
                ldsm4(h0, h1, h2, h3, Bh + idx);
                ldsm4(lo0, lo1, lo2, lo3, Bl + idx);
                unsigned bh[2], bl[2];
                bh[0] = h0;  bh[1] = h1;  bl[0] = lo0; bl[1] = lo1;
#pragma unroll
                for (int mf = 0; mf < 2; mf++) {
                    mma_bf16(acc[mf][2 * nf2], ah[mf], bl);
                    mma_bf16(acc[mf][2 * nf2], al[mf], bh);
                    mma_bf16(acc[mf][2 * nf2], ah[mf], bh);
                }
                bh[0] = h2;  bh[1] = h3;  bl[0] = lo2; bl[1] = lo3;
#pragma unroll
                for (int mf = 0; mf < 2; mf++) {
                    mma_bf16(acc[mf][2 * nf2 + 1], ah[mf], bl);
                    mma_bf16(acc[mf][2 * nf2 + 1], al[mf], bh);
                    mma_bf16(acc[mf][2 * nf2 + 1], ah[mf], bh);
                }
            }
        }
        __syncthreads();
    }

#pragma unroll
    for (int mf = 0; mf < 2; mf++) {
        const int row = m0 + wm * 32 + mf * 16 + g;
#pragma unroll
        for (int nf = 0; nf < 8; nf++) {
            const int col = n0 + wn * 64 + nf * 8 + 2 * lam;
            float b0 = bo[col];
            float b1 = bo[col + 1];
            float2 v0 = make_float2(acc[mf][nf][0] + b0, acc[mf][nf][1] + b1);
            float2 v1 = make_float2(acc[mf][nf][2] + b0, acc[mf][nf][3] + b1);
            *reinterpret_cast<float2*>(g_out + (size_t)row * EM + col) = v0;
            *reinterpret_cast<float2*>(g_out + (size_t)(row + 8) * EM + col) = v1;
        }
    }
}

// ---------------- kernel 5: residual + LayerNorm ----------------
__device__ __forceinline__ float block_sum_256(float val, float* sh)
{
    const int lane = threadIdx.x & 31;
    const int w    = threadIdx.x >> 5;
#pragma unroll
    for (int o = 16; o > 0; o >>= 1) val += __shfl_xor_sync(0xffffffffu, val, o);
    if (lane == 0) sh[w] = val;
    __syncthreads();
    if (w == 0) {
        float t = (lane < 8) ? sh[lane] : 0.f;
#pragma unroll
        for (int o = 4; o > 0; o >>= 1) t += __shfl_xor_sync(0xffffffffu, t, o);
        if (lane == 0) sh[0] = t;
    }
    __syncthreads();
    const float r = sh[0];
    __syncthreads();
    return r;
}

__global__ __launch_bounds__(256) void k_ln(const float* __restrict__ x,
                                            const float* __restrict__ gamma,
                                            const float* __restrict__ beta,
                                            float* __restrict__ out)
{
    __shared__ float sh[8];
    const int srow = blockIdx.x;
    const float* orow = g_out + (size_t)srow * EM;
    const float* xrow = x + (size_t)srow * EM;

    float v[4];
    float sum = 0.f;
#pragma unroll
    for (int i = 0; i < 4; i++) {
        const int c = threadIdx.x + i * 256;
        v[i] = orow[c] + xrow[c];
        sum += v[i];
    }
    const float mean = block_sum_256(sum, sh) * (1.f / EM);

    float var = 0.f;
#pragma unroll
    for (int i = 0; i < 4; i++) {
        const float d = v[i] - mean;
        var += d * d;
    }
    const float rstd = rsqrtf(block_sum_256(var, sh) * (1.f / EM) + 1e-5f);

#pragma unroll
    for (int i = 0; i < 4; i++) {
        const int c = threadIdx.x + i * 256;
        out[(size_t)srow * EM + c] = (v[i] - mean) * rstd * gamma[c] + beta[c];
    }
}

// ---------------- launch ----------------
extern "C" void kernel_launch(void* const* d_in, const int* in_sizes, int n_in,
                              void* d_out, int out_size)
{
    const float* x     = (const float*)d_in[0];
    const float* Wk    = (const float*)d_in[1];
    const float* Wq    = (const float*)d_in[2];
    const float* Wv    = (const float*)d_in[3];
    const float* hWk   = (const float*)d_in[4];
    const float* hbk   = (const float*)d_in[5];
    const float* hWv   = (const float*)d_in[6];
    const float* hbv   = (const float*)d_in[7];
    const float* hWq   = (const float*)d_in[8];
    const float* hbq   = (const float*)d_in[9];
    const float* Wo    = (const float*)d_in[10];
    const float* bo    = (const float*)d_in[11];
    const float* gamma = (const float*)d_in[12];
    const float* beta  = (const float*)d_in[13];
    float* out = (float*)d_out;

    const int attn_smem = 3 * STAGE_W * 4;
    cudaFuncSetAttribute(k_attn, cudaFuncAttributeMaxDynamicSharedMemorySize, attn_smem);
    const int oproj_smem = 2 * OSTAGE * 4;
    cudaFuncSetAttribute(k_outproj, cudaFuncAttributeMaxDynamicSharedMemorySize, oproj_smem);

    k_splitW<<<EM, 128>>>(Wo);
    k_proj<<<dim3(1, SQ / 32, 3), 128>>>(x, Wk, Wq, Wv);
    k_headlin<<<dim3(1, SQ / 64, 48), 128>>>(hWk, hbk, hWv, hbv, hWq, hbq);
    k_attn<<<dim3(SQ / 128, NH), 256, attn_smem>>>();
    k_outproj<<<dim3(EM / 128, SQ / 128), 256, oproj_smem>>>(bo);
    k_ln<<<SQ, 256>>>(x, gamma, beta, out);
}

// round 15
// speedup vs baseline: 1.4155x; 1.4155x over previous
#include <cuda_runtime.h>
#include <math.h>

#define SQ 2048
#define EM 1024
#define DM 64
#define NH 16

// ---------------- scratch: packed bf16x2 hi/lo pair arrays ----------------
__device__ __align__(16) unsigned g_pKh[SQ * 32], g_pKl[SQ * 32];
__device__ __align__(16) unsigned g_pQh[SQ * 32], g_pQl[SQ * 32];
__device__ __align__(16) unsigned g_pVh[SQ * 32], g_pVl[SQ * 32];
__device__ __align__(16) unsigned g_hKh[NH * SQ * 32], g_hKl[NH * SQ * 32];
__device__ __align__(16) unsigned g_hQh[NH * SQ * 32], g_hQl[NH * SQ * 32];
__device__ __align__(16) float    g_Vh[NH * SQ * DM];
__device__ __align__(16) unsigned g_tVh[NH * DM * (SQ / 2)], g_tVl[NH * DM * (SQ / 2)];
__device__ __align__(16) unsigned g_ch[SQ * (EM / 2)], g_cl[SQ * (EM / 2)];
__device__ __align__(16) unsigned g_Woh[EM * (EM / 2)], g_Wol[EM * (EM / 2)];
__device__ __align__(16) float    g_out[SQ * EM];

// ---------------- bf16 split helpers ----------------
__device__ __forceinline__ unsigned pk2(float x, float y) {
    unsigned r;
    asm("cvt.rn.bf16x2.f32 %0, %1, %2;" : "=r"(r) : "f"(y), "f"(x));
    return r;
}

__device__ __forceinline__ void sp2(float x, float y, unsigned& hi, unsigned& lo) {
    unsigned ux = __float_as_uint(x), uy = __float_as_uint(y);
    hi = __byte_perm(ux, uy, 0x7632);
    float rx = x - __uint_as_float(ux & 0xffff0000u);
    float ry = y - __uint_as_float(uy & 0xffff0000u);
    lo = pk2(rx, ry);
}

__device__ __forceinline__ void mma_bf16(float* d, const unsigned* a, const unsigned* b) {
    asm volatile(
        "mma.sync.aligned.m16n8k16.row.col.f32.bf16.bf16.f32 "
        "{%0,%1,%2,%3},{%4,%5,%6,%7},{%8,%9},{%0,%1,%2,%3};"
        : "+f"(d[0]), "+f"(d[1]), "+f"(d[2]), "+f"(d[3])
        : "r"(a[0]), "r"(a[1]), "r"(a[2]), "r"(a[3]), "r"(b[0]), "r"(b[1]));
}

__device__ __forceinline__ void cp16(unsigned* smem_dst, const void* gsrc) {
    unsigned daddr = (unsigned)__cvta_generic_to_shared(smem_dst);
    asm volatile("cp.async.cg.shared.global [%0], [%1], 16;" :: "r"(daddr), "l"(gsrc));
}

__device__ __forceinline__ void ldsm4(unsigned& r0, unsigned& r1, unsigned& r2, unsigned& r3,
                                      const unsigned* p) {
    unsigned addr = (unsigned)__cvta_generic_to_shared(p);
    asm volatile("ldmatrix.sync.aligned.m8n8.x4.shared.b16 {%0,%1,%2,%3}, [%4];"
                 : "=r"(r0), "=r"(r1), "=r"(r2), "=r"(r3) : "r"(addr));
}

// ======== split-bf16 3-term GEMM: C = A @ B^T (+bias), BK=32 ========
#define SK 20

template <int BM, int BN, int WM, int WN, bool ASPLIT, bool BSPLIT, bool OUTPAIR>
__device__ __forceinline__ void gemm3x(
    const float* A, const unsigned* Aph, const unsigned* Apl, int lda,
    const float* B, const unsigned* Bph, const unsigned* Bpl, int ldb,
    const float* bias,
    float* C, unsigned* Cph, unsigned* Cpl, int ldc,
    float oscale, int Kd, int m0, int n0,
    unsigned* Ah, unsigned* Al, unsigned* Bh, unsigned* Bl)
{
    constexpr int NT = WM * WN * 32;
    constexpr int MF = BM / (WM * 16);
    constexpr int NF = BN / (WN * 8);
    const int tid  = threadIdx.x;
    const int lane = tid & 31;
    const int warp = tid >> 5;
    const int wm   = warp % WM;
    const int wn   = warp / WM;
    const int g    = lane >> 2;
    const int lam  = lane & 3;

    float acc[MF][NF][4];
#pragma unroll
    for (int mf = 0; mf < MF; mf++)
#pragma unroll
        for (int nf = 0; nf < NF; nf++)
#pragma unroll
            for (int i = 0; i < 4; i++) acc[mf][nf][i] = 0.f;

    for (int k0 = 0; k0 < Kd; k0 += 32) {
        __syncthreads();
        if (ASPLIT) {
#pragma unroll
            for (int e = tid; e < BM * 4; e += NT) {
                int r = e >> 2, c = e & 3;
                size_t off = (size_t)(m0 + r) * lda + (k0 >> 1) + c * 4;
                *reinterpret_cast<uint4*>(Ah + r * SK + c * 4) = *reinterpret_cast<const uint4*>(Aph + off);
                *reinterpret_cast<uint4*>(Al + r * SK + c * 4) = *reinterpret_cast<const uint4*>(Apl + off);
            }
        } else {
#pragma unroll
            for (int e = tid; e < BM * 8; e += NT) {
                int r = e >> 3, c4 = e & 7;
                float4 v = *reinterpret_cast<const float4*>(A + (size_t)(m0 + r) * lda + k0 + c4 * 4);
                sp2(v.x, v.y, Ah[r * SK + c4 * 2 + 0], Al[r * SK + c4 * 2 + 0]);
                sp2(v.z, v.w, Ah[r * SK + c4 * 2 + 1], Al[r * SK + c4 * 2 + 1]);
            }
        }
        if (BSPLIT) {
#pragma unroll
            for (int e = tid; e < BN * 4; e += NT) {
                int r = e >> 2, c = e & 3;
                size_t off = (size_t)(n0 + r) * ldb + (k0 >> 1) + c * 4;
                *reinterpret_cast<uint4*>(Bh + r * SK + c * 4) = *reinterpret_cast<const uint4*>(Bph + off);
                *reinterpret_cast<uint4*>(Bl + r * SK + c * 4) = *reinterpret_cast<const uint4*>(Bpl + off);
            }
        } else {
#pragma unroll
            for (int e = tid; e < BN * 8; e += NT) {
                int r = e >> 3, c4 = e & 7;
                float4 v = *reinterpret_cast<const float4*>(B + (size_t)(n0 + r) * ldb + k0 + c4 * 4);
                sp2(v.x, v.y, Bh[r * SK + c4 * 2 + 0], Bl[r * SK + c4 * 2 + 0]);
                sp2(v.z, v.w, Bh[r * SK + c4 * 2 + 1], Bl[r * SK + c4 * 2 + 1]);
            }
        }
        __syncthreads();

#pragma unroll
        for (int kc = 0; kc < 2; kc++) {
            unsigned ah[MF][4], al[MF][4];
#pragma unroll
            for (int mf = 0; mf < MF; mf++) {
                const int r = wm * (MF * 16) + mf * 16 + g;
                ah[mf][0] = Ah[r * SK + kc * 8 + lam];
                ah[mf][1] = Ah[(r + 8) * SK + kc * 8 + lam];
                ah[mf][2] = Ah[r * SK + kc * 8 + lam + 4];
                ah[mf][3] = Ah[(r + 8) * SK + kc * 8 + lam + 4];
                al[mf][0] = Al[r * SK + kc * 8 + lam];
                al[mf][1] = Al[(r + 8) * SK + kc * 8 + lam];
                al[mf][2] = Al[r * SK + kc * 8 + lam + 4];
                al[mf][3] = Al[(r + 8) * SK + kc * 8 + lam + 4];
            }
#pragma unroll
            for (int nf = 0; nf < NF; nf++) {
                const int rb = wn * (NF * 8) + nf * 8 + g;
                unsigned bh[2], bl[2];
                bh[0] = Bh[rb * SK + kc * 8 + lam];
                bh[1] = Bh[rb * SK + kc * 8 + lam + 4];
                bl[0] = Bl[rb * SK + kc * 8 + lam];
                bl[1] = Bl[rb * SK + kc * 8 + lam + 4];
#pragma unroll
                for (int mf = 0; mf < MF; mf++) {
                    mma_bf16(acc[mf][nf], ah[mf], bl);
                    mma_bf16(acc[mf][nf], al[mf], bh);
                    mma_bf16(acc[mf][nf], ah[mf], bh);
                }
            }
        }
    }

#pragma unroll
    for (int mf = 0; mf < MF; mf++) {
        const int row = m0 + wm * (MF * 16) + mf * 16 + g;
#pragma unroll
        for (int nf = 0; nf < NF; nf++) {
            if (OUTPAIR) {
                const int pc = (n0 >> 1) + wn * (NF * 4) + nf * 4 + lam;
                float b0 = bias ? bias[2 * pc] : 0.f;
                float b1 = bias ? bias[2 * pc + 1] : 0.f;
                unsigned hi, lo;
                sp2((acc[mf][nf][0] + b0) * oscale, (acc[mf][nf][1] + b1) * oscale, hi, lo);
                Cph[(size_t)row * ldc + pc] = hi;
                Cpl[(size_t)row * ldc + pc] = lo;
                sp2((acc[mf][nf][2] + b0) * oscale, (acc[mf][nf][3] + b1) * oscale, hi, lo);
                Cph[(size_t)(row + 8) * ldc + pc] = hi;
                Cpl[(size_t)(row + 8) * ldc + pc] = lo;
            } else {
                const int col = n0 + wn * (NF * 8) + nf * 8 + 2 * lam;
                float b0 = bias ? bias[col] : 0.f;
                float b1 = bias ? bias[col + 1] : 0.f;
                float2 v0 = make_float2(acc[mf][nf][0] + b0, acc[mf][nf][1] + b1);
                float2 v1 = make_float2(acc[mf][nf][2] + b0, acc[mf][nf][3] + b1);
                *reinterpret_cast<float2*>(C + (size_t)row * ldc + col) = v0;
                *reinterpret_cast<float2*>(C + (size_t)(row + 8) * ldc + col) = v1;
            }
        }
    }
}

// ---------------- kernel 0: pre-split Wo ----------------
__global__ __launch_bounds__(128) void k_splitW(const float* __restrict__ Wo)
{
    const int r = blockIdx.x;
#pragma unroll
    for (int i = 0; i < 2; i++) {
        int c4 = threadIdx.x + i * 128;
        float4 v = *reinterpret_cast<const float4*>(Wo + (size_t)r * EM + c4 * 4);
        unsigned h0, l0, h1, l1;
        sp2(v.x, v.y, h0, l0);
        sp2(v.z, v.w, h1, l1);
        g_Woh[(size_t)r * 512 + c4 * 2 + 0] = h0;
        g_Wol[(size_t)r * 512 + c4 * 2 + 0] = l0;
        g_Woh[(size_t)r * 512 + c4 * 2 + 1] = h1;
        g_Wol[(size_t)r * 512 + c4 * 2 + 1] = l1;
    }
}

// ---------------- kernel 1: shared projections (BM=32 -> 192 CTAs) ----------------
__global__ __launch_bounds__(128) void k_proj(const float* __restrict__ x,
                                              const float* __restrict__ Wk,
                                              const float* __restrict__ Wq,
                                              const float* __restrict__ Wv)
{
    __shared__ unsigned Ah[32 * SK], Al[32 * SK], Bh[64 * SK], Bl[64 * SK];
    const float* W;
    unsigned *Ch, *Cl;
    if (blockIdx.z == 0)      { W = Wk; Ch = g_pKh; Cl = g_pKl; }
    else if (blockIdx.z == 1) { W = Wq; Ch = g_pQh; Cl = g_pQl; }
    else                      { W = Wv; Ch = g_pVh; Cl = g_pVl; }
    gemm3x<32, 64, 1, 4, false, false, true>(
        x, nullptr, nullptr, EM, W, nullptr, nullptr, EM, nullptr,
        nullptr, Ch, Cl, 32, 1.f, EM, blockIdx.y * 32, 0, Ah, Al, Bh, Bl);
}

// ---------------- kernel 2: per-head linears, single-shot K=64, LDSM frags -------
#define HS 36

__global__ __launch_bounds__(128) void k_headlin(const float* __restrict__ hWk,
                                                 const float* __restrict__ hbk,
                                                 const float* __restrict__ hWv,
                                                 const float* __restrict__ hbv,
                                                 const float* __restrict__ hWq,
                                                 const float* __restrict__ hbq)
{
    __shared__ unsigned Ah[64 * HS], Al[64 * HS], Bh[64 * HS], Bl[64 * HS];
    const int z = blockIdx.z;
    const int t = z >> 4;
    const int h = z & 15;
    const int m0 = blockIdx.y * 64;
    const int tid  = threadIdx.x;
    const int lane = tid & 31;
    const int warp = tid >> 5;
    const int wm   = warp & 1;
    const int wn   = warp >> 1;
    const int g    = lane >> 2;
    const int lam  = lane & 3;

    const unsigned *Aph, *Apl;
    const float *B, *bias;
    float oscale = 1.f;
    if (t == 0)      { Aph = g_pKh; Apl = g_pKl; B = hWk + h * DM * DM; bias = hbk + h * DM; }
    else if (t == 2) { Aph = g_pQh; Apl = g_pQl; B = hWq + h * DM * DM; bias = hbq + h * DM; oscale = 0.125f; }
    else             { Aph = g_pVh; Apl = g_pVl; B = hWv + h * DM * DM; bias = hbv + h * DM; }

#pragma unroll
    for (int i = 0; i < 4; i++) {
        int e = tid + i * 128;
        int r = e >> 3, c = e & 7;
        size_t off = (size_t)(m0 + r) * 32 + c * 4;
        *reinterpret_cast<uint4*>(Ah + r * HS + c * 4) = *reinterpret_cast<const uint4*>(Aph + off);
        *reinterpret_cast<uint4*>(Al + r * HS + c * 4) = *reinterpret_cast<const uint4*>(Apl + off);
    }
#pragma unroll
    for (int i = 0; i < 8; i++) {
        int e = tid + i * 128;
        int r = e >> 4, c4 = e & 15;
        float4 v = *reinterpret_cast<const float4*>(B + (size_t)r * DM + c4 * 4);
        sp2(v.x, v.y, Bh[r * HS + c4 * 2 + 0], Bl[r * HS + c4 * 2 + 0]);
        sp2(v.z, v.w, Bh[r * HS + c4 * 2 + 1], Bl[r * HS + c4 * 2 + 1]);
    }
    __syncthreads();

    const int lrowA = ((lane >> 3) & 1) * 8 + (lane & 7);
    const int lcolA = (lane >> 4) * 4;
    const int quad  = lane >> 3;
    const int lrowB = (quad >> 1) * 8 + (lane & 7);
    const int lcolB = (quad & 1) * 4;

    float acc[2][4][4];
#pragma unroll
    for (int mf = 0; mf < 2; mf++)
#pragma unroll
        for (int nf = 0; nf < 4; nf++)
#pragma unroll
            for (int i = 0; i < 4; i++) acc[mf][nf][i] = 0.f;

#pragma unroll
    for (int kc = 0; kc < 4; kc++) {
        unsigned ah[2][4], al[2][4];
#pragma unroll
        for (int mf = 0; mf < 2; mf++) {
            const int idx = (wm * 32 + mf * 16 + lrowA) * HS + kc * 8 + lcolA;
            ldsm4(ah[mf][0], ah[mf][1], ah[mf][2], ah[mf][3], Ah + idx);
            ldsm4(al[mf][0], al[mf][1], al[mf][2], al[mf][3], Al + idx);
        }
#pragma unroll
        for (int nf2 = 0; nf2 < 2; nf2++) {
            const int idx = (wn * 32 + nf2 * 16 + lrowB) * HS + kc * 8 + lcolB;
            unsigned h0, h1, h2, h3, lo0, lo1, lo2, lo3;
            ldsm4(h0, h1, h2, h3, Bh + idx);
            ldsm4(lo0, lo1, lo2, lo3, Bl + idx);
            unsigned bh[2], bl[2];
            bh[0] = h0;  bh[1] = h1;  bl[0] = lo0; bl[1] = lo1;
#pragma unroll
            for (int mf = 0; mf < 2; mf++) {
                mma_bf16(acc[mf][2 * nf2], ah[mf], bl);
                mma_bf16(acc[mf][2 * nf2], al[mf], bh);
                mma_bf16(acc[mf][2 * nf2], ah[mf], bh);
            }
            bh[0] = h2;  bh[1] = h3;  bl[0] = lo2; bl[1] = lo3;
#pragma unroll
            for (int mf = 0; mf < 2; mf++) {
                mma_bf16(acc[mf][2 * nf2 + 1], ah[mf], bl);
                mma_bf16(acc[mf][2 * nf2 + 1], al[mf], bh);
                mma_bf16(acc[mf][2 * nf2 + 1], ah[mf], bh);
            }
        }
    }

    // epilogue
    if (t == 1) {
        float* C = g_Vh + (size_t)h * SQ * DM;
#pragma unroll
        for (int mf = 0; mf < 2; mf++) {
            const int row = m0 + wm * 32 + mf * 16 + g;
#pragma unroll
            for (int nf = 0; nf < 4; nf++) {
                const int col = wn * 32 + nf * 8 + 2 * lam;
                float b0 = bias[col], b1 = bias[col + 1];
                float2 v0 = make_float2(acc[mf][nf][0] + b0, acc[mf][nf][1] + b1);
                float2 v1 = make_float2(acc[mf][nf][2] + b0, acc[mf][nf][3] + b1);
                *reinterpret_cast<float2*>(C + (size_t)row * DM + col) = v0;
                *reinterpret_cast<float2*>(C + (size_t)(row + 8) * DM + col) = v1;
            }
        }
    } else {
        unsigned* Cph = (t == 0) ? g_hKh + (size_t)h * SQ * 32 : g_hQh + (size_t)h * SQ * 32;
        unsigned* Cpl = (t == 0) ? g_hKl + (size_t)h * SQ * 32 : g_hQl + (size_t)h * SQ * 32;
#pragma unroll
        for (int mf = 0; mf < 2; mf++) {
            const int row = m0 + wm * 32 + mf * 16 + g;
#pragma unroll
            for (int nf = 0; nf < 4; nf++) {
                const int pc = wn * 16 + nf * 4 + lam;
                float b0 = bias[2 * pc], b1 = bias[2 * pc + 1];
                unsigned hi, lo;
                sp2((acc[mf][nf][0] + b0) * oscale, (acc[mf][nf][1] + b1) * oscale, hi, lo);
                Cph[(size_t)row * 32 + pc] = hi;
                Cpl[(size_t)row * 32 + pc] = lo;
                sp2((acc[mf][nf][2] + b0) * oscale, (acc[mf][nf][3] + b1) * oscale, hi, lo);
                Cph[(size_t)(row + 8) * 32 + pc] = hi;
                Cpl[(size_t)(row + 8) * 32 + pc] = lo;
            }
        }
    }
}

// ---------------- kernel 2b: transpose Vh -> split Vt pairs [h][d][s/2] -------
__global__ void k_transpose()
{
    __shared__ float t[32][33];
    const int h  = blockIdx.z;
    const int s0 = blockIdx.x * 32;
    const int d0 = blockIdx.y * 32;
    const int tx = threadIdx.x, ty = threadIdx.y;
    const float* src = g_Vh + (size_t)h * SQ * DM;
#pragma unroll
    for (int i = 0; i < 4; i++)
        t[ty + i * 8][tx] = src[(size_t)(s0 + ty + i * 8) * DM + d0 + tx];
    __syncthreads();
    const int tid = ty * 32 + tx;
#pragma unroll
    for (int i = 0; i < 2; i++) {
        int o  = tid + i * 256;
        int dl = o >> 4, p = o & 15;
        unsigned hi, lo;
        sp2(t[2 * p][dl], t[2 * p + 1][dl], hi, lo);
        size_t idx = ((size_t)h * DM + d0 + dl) * (SQ / 2) + (s0 >> 1) + p;
        g_tVh[idx] = hi;
        g_tVl[idx] = lo;
    }
}

// -- kernel 3: flash attention, 256 thr / 128 q-rows, cp.async 3-stage, LDSM frags --
#define AS 36
#define TW (64 * AS)
#define STAGE_W (4 * TW)
#define NIT (SQ / 64)

__global__ __launch_bounds__(256, 1) void k_attn()
{
    extern __shared__ unsigned sm[];
    const int h    = blockIdx.y;
    const int tid  = threadIdx.x;
    const int lane = tid & 31;
    const int warp = tid >> 5;
    const int g    = lane >> 2;
    const int lam  = lane & 3;
    const int q0   = blockIdx.x * 128 + warp * 16;

    const int quad = lane >> 3;
    const int lr   = lane & 7;
    const int lrow = (quad >> 1) * 8 + lr;
    const int lcol = (quad & 1) * 4;

    const unsigned* Qh_ = g_hQh + (size_t)h * SQ * 32;
    const unsigned* Ql_ = g_hQl + (size_t)h * SQ * 32;
    const unsigned* Kh_ = g_hKh + (size_t)h * SQ * 32;
    const unsigned* Kl_ = g_hKl + (size_t)h * SQ * 32;
    const unsigned* Vh_ = g_tVh + (size_t)h * DM * (SQ / 2);
    const unsigned* Vl_ = g_tVl + (size_t)h * DM * (SQ / 2);

    unsigned qh[4][4], ql[4][4];
#pragma unroll
    for (int kc = 0; kc < 4; kc++) {
        qh[kc][0] = Qh_[(size_t)(q0 + g) * 32 + kc * 8 + lam];
        qh[kc][1] = Qh_[(size_t)(q0 + g + 8) * 32 + kc * 8 + lam];
        qh[kc][2] = Qh_[(size_t)(q0 + g) * 32 + kc * 8 + 4 + lam];
        qh[kc][3] = Qh_[(size_t)(q0 + g + 8) * 32 + kc * 8 + 4 + lam];
        ql[kc][0] = Ql_[(size_t)(q0 + g) * 32 + kc * 8 + lam];
        ql[kc][1] = Ql_[(size_t)(q0 + g + 8) * 32 + kc * 8 + lam];
        ql[kc][2] = Ql_[(size_t)(q0 + g) * 32 + kc * 8 + 4 + lam];
        ql[kc][3] = Ql_[(size_t)(q0 + g + 8) * 32 + kc * 8 + 4 + lam];
    }

    float o[8][4];
#pragma unroll
    for (int nf = 0; nf < 8; nf++)
#pragma unroll
        for (int i = 0; i < 4; i++) o[nf][i] = 0.f;
    float m0r = -1e30f, m1r = -1e30f, l0 = 0.f, l1 = 0.f;

    auto fill = [&](int stage, int t0) {
        unsigned* bKh = sm + stage * STAGE_W;
        unsigned* bKl = bKh + TW;
        unsigned* bVh = bKl + TW;
        unsigned* bVl = bVh + TW;
#pragma unroll
        for (int i = 0; i < 2; i++) {
            int e = tid + i * 256;
            int r = e >> 3, c = e & 7;
            size_t ko = (size_t)(t0 + r) * 32 + c * 4;
            cp16(bKh + r * AS + c * 4, Kh_ + ko);
            cp16(bKl + r * AS + c * 4, Kl_ + ko);
            size_t vo = (size_t)r * (SQ / 2) + (t0 >> 1) + c * 4;
            cp16(bVh + r * AS + c * 4, Vh_ + vo);
            cp16(bVl + r * AS + c * 4, Vl_ + vo);
        }
        asm volatile("cp.async.commit_group;");
    };

    fill(0, 0);
    fill(1, 64);

    for (int it = 0; it < NIT; it++) {
        const int cur = it % 3;
        if (it + 2 < NIT) {
            fill((it + 2) % 3, (it + 2) * 64);
            asm volatile("cp.async.wait_group 2;");
        } else if (it + 1 < NIT) {
            asm volatile("cp.async.wait_group 1;");
        } else {
            asm volatile("cp.async.wait_group 0;");
        }
        __syncthreads();

        const unsigned* sKh = sm + cur * STAGE_W;
        const unsigned* sKl = sKh + TW;
        const unsigned* sVh = sKl + TW;
        const unsigned* sVl = sVh + TW;

        float s[8][4];
#pragma unroll
        for (int nf = 0; nf < 8; nf++)
            s[nf][0] = s[nf][1] = s[nf][2] = s[nf][3] = 0.f;
#pragma unroll
        for (int kc = 0; kc < 4; kc++) {
#pragma unroll
            for (int nf2 = 0; nf2 < 4; nf2++) {
                const int idx = (nf2 * 16 + lrow) * AS + kc * 8 + lcol;
                unsigned h0, h1, h2, h3, lo0, lo1, lo2, lo3;
                ldsm4(h0, h1, h2, h3, sKh + idx);
                ldsm4(lo0, lo1, lo2, lo3, sKl + idx);
                unsigned bh[2], bl[2];
                bh[0] = h0;  bh[1] = h1;  bl[0] = lo0; bl[1] = lo1;
                mma_bf16(s[2 * nf2], qh[kc], bl);
                mma_bf16(s[2 * nf2], ql[kc], bh);
                mma_bf16(s[2 * nf2], qh[kc], bh);
                bh[0] = h2;  bh[1] = h3;  bl[0] = lo2; bl[1] = lo3;
                mma_bf16(s[2 * nf2 + 1], qh[kc], bl);
                mma_bf16(s[2 * nf2 + 1], ql[kc], bh);
                mma_bf16(s[2 * nf2 + 1], qh[kc], bh);
            }
        }

        float mx0 = m0r, mx1 = m1r;
#pragma unroll
        for (int nf = 0; nf < 8; nf++) {
            mx0 = fmaxf(mx0, fmaxf(s[nf][0], s[nf][1]));
            mx1 = fmaxf(mx1, fmaxf(s[nf][2], s[nf][3]));
        }
        mx0 = fmaxf(mx0, __shfl_xor_sync(0xffffffffu, mx0, 1));
        mx0 = fmaxf(mx0, __shfl_xor_sync(0xffffffffu, mx0, 2));
        mx1 = fmaxf(mx1, __shfl_xor_sync(0xffffffffu, mx1, 1));
        mx1 = fmaxf(mx1, __shfl_xor_sync(0xffffffffu, mx1, 2));

        const float c0 = __expf(m0r - mx0);
        const float c1 = __expf(m1r - mx1);
        m0r = mx0; m1r = mx1;

        float ls0 = 0.f, ls1 = 0.f;
#pragma unroll
        for (int nf = 0; nf < 8; nf++) {
            s[nf][0] = __expf(s[nf][0] - mx0);
            s[nf][1] = __expf(s[nf][1] - mx0);
            s[nf][2] = __expf(s[nf][2] - mx1);
            s[nf][3] = __expf(s[nf][3] - mx1);
            ls0 += s[nf][0] + s[nf][1];
            ls1 += s[nf][2] + s[nf][3];
        }
        ls0 += __shfl_xor_sync(0xffffffffu, ls0, 1);
        ls0 += __shfl_xor_sync(0xffffffffu, ls0, 2);
        ls1 += __shfl_xor_sync(0xffffffffu, ls1, 1);
        ls1 += __shfl_xor_sync(0xffffffffu, ls1, 2);
        l0 = l0 * c0 + ls0;
        l1 = l1 * c1 + ls1;
#pragma unroll
        for (int nf = 0; nf < 8; nf++) {
            o[nf][0] *= c0; o[nf][1] *= c0;
            o[nf][2] *= c1; o[nf][3] *= c1;
        }

        unsigned ph[4][4], pl[4][4];
#pragma unroll
        for (int kc = 0; kc < 4; kc++) {
            sp2(s[2 * kc][0],     s[2 * kc][1],     ph[kc][0], pl[kc][0]);
            sp2(s[2 * kc][2],     s[2 * kc][3],     ph[kc][1], pl[kc][1]);
            sp2(s[2 * kc + 1][0], s[2 * kc + 1][1], ph[kc][2], pl[kc][2]);
            sp2(s[2 * kc + 1][2], s[2 * kc + 1][3], ph[kc][3], pl[kc][3]);
        }

#pragma unroll
        for (int kc = 0; kc < 4; kc++) {
#pragma unroll
            for (int nf2 = 0; nf2 < 4; nf2++) {
                const int idx = (nf2 * 16 + lrow) * AS + kc * 8 + lcol;
                unsigned h0, h1, h2, h3, lo0, lo1, lo2, lo3;
                ldsm4(h0, h1, h2, h3, sVh + idx);
                ldsm4(lo0, lo1, lo2, lo3, sVl + idx);
                unsigned bh[2], bl[2];
                bh[0] = h0;  bh[1] = h1;  bl[0] = lo0; bl[1] = lo1;
                mma_bf16(o[2 * nf2], ph[kc], bl);
                mma_bf16(o[2 * nf2], pl[kc], bh);
                mma_bf16(o[2 * nf2], ph[kc], bh);
                bh[0] = h2;  bh[1] = h3;  bl[0] = lo2; bl[1] = lo3;
                mma_bf16(o[2 * nf2 + 1], ph[kc], bl);
                mma_bf16(o[2 * nf2 + 1], pl[kc], bh);
                mma_bf16(o[2 * nf2 + 1], ph[kc], bh);
            }
        }
        __syncthreads();
    }

    const float inv0 = 1.f / l0;
    const float inv1 = 1.f / l1;
#pragma unroll
    for (int nf = 0; nf < 8; nf++) {
        const int pc = h * 32 + nf * 4 + lam;
        unsigned hi, lo;
        sp2(o[nf][0] * inv0, o[nf][1] * inv0, hi, lo);
        g_ch[(size_t)(q0 + g) * 512 + pc] = hi;
        g_cl[(size_t)(q0 + g) * 512 + pc] = lo;
        sp2(o[nf][2] * inv1, o[nf][3] * inv1, hi, lo);
        g_ch[(size_t)(q0 + g + 8) * 512 + pc] = hi;
        g_cl[(size_t)(q0 + g + 8) * 512 + pc] = lo;
    }
}

// ---------- kernel 4: out-proj, cp.async 2-stage pipelined, LDSM frags ----------
#define OS 20
#define OTW (128 * OS)
#define OSTAGE (4 * OTW)

__global__ __launch_bounds__(256) void k_outproj(const float* __restrict__ bo)
{
    extern __shared__ unsigned sm[];
    const int tid  = threadIdx.x;
    const int lane = tid & 31;
    const int warp = tid >> 5;
    const int wm   = warp % 4;
    const int wn   = warp / 4;
    const int g    = lane >> 2;
    const int lam  = lane & 3;
    const int m0   = blockIdx.y * 128;
    const int n0   = blockIdx.x * 128;

    const int lrowA = ((lane >> 3) & 1) * 8 + (lane & 7);
    const int lcolA = (lane >> 4) * 4;
    const int quad  = lane >> 3;
    const int lrowB = (quad >> 1) * 8 + (lane & 7);
    const int lcolB = (quad & 1) * 4;

    float acc[2][8][4];
#pragma unroll
    for (int mf = 0; mf < 2; mf++)
#pragma unroll
        for (int nf = 0; nf < 8; nf++)
#pragma unroll
            for (int i = 0; i < 4; i++) acc[mf][nf][i] = 0.f;

    auto fill = [&](int stage, int k0) {
        unsigned* Ah = sm + stage * OSTAGE;
        unsigned* Al = Ah + OTW;
        unsigned* Bh = Al + OTW;
        unsigned* Bl = Bh + OTW;
#pragma unroll
        for (int i = 0; i < 2; i++) {
            int e = tid + i * 256;
            int r = e >> 2, c = e & 3;
            size_t ao = (size_t)(m0 + r) * 512 + (k0 >> 1) + c * 4;
            cp16(Ah + r * OS + c * 4, g_ch + ao);
            cp16(Al + r * OS + c * 4, g_cl + ao);
            size_t bo_ = (size_t)(n0 + r) * 512 + (k0 >> 1) + c * 4;
            cp16(Bh + r * OS + c * 4, g_Woh + bo_);
            cp16(Bl + r * OS + c * 4, g_Wol + bo_);
        }
        asm volatile("cp.async.commit_group;");
    };

    fill(0, 0);

    for (int it = 0; it < EM / 32; it++) {
        const int cur = it & 1;
        if (it + 1 < EM / 32) {
            fill(cur ^ 1, (it + 1) * 32);
            asm volatile("cp.async.wait_group 1;");
        } else {
            asm volatile("cp.async.wait_group 0;");
        }
        __syncthreads();

        const unsigned* Ah = sm + cur * OSTAGE;
        const unsigned* Al = Ah + OTW;
        const unsigned* Bh = Al + OTW;
        const unsigned* Bl = Bh + OTW;

#pragma unroll
        for (int kc = 0; kc < 2; kc++) {
            unsigned ah[2][4], al[2][4];
#pragma unroll
            for (int mf = 0; mf < 2; mf++) {
                const int idx = (wm * 32 + mf * 16 + lrowA) * OS + kc * 8 + lcolA;
                ldsm4(ah[mf][0], ah[mf][1], ah[mf][2], ah[mf][3], Ah + idx);
                ldsm4(al[mf][0], al[mf][1], al[mf][2], al[mf][3], Al + idx);
            }
#pragma unroll
            for (int nf2 = 0; nf2 < 4; nf2++) {
                const int idx = (wn * 64 + nf2 * 16 + lrowB) * OS + kc * 8 + lcolB;
                unsigned h0, h1, h2, h3, lo0, lo1, lo2, lo3;
                ldsm4(h0, h1, h2, h3, Bh + idx);
                ldsm4(lo0, lo1, lo2, lo3, Bl + idx);
                unsigned bh[2], bl[2];
                bh[0] = h0;  bh[1] = h1;  bl[0] = lo0; bl[1] = lo1;
#pragma unroll
                for (int mf = 0; mf < 2; mf++) {
                    mma_bf16(acc[mf][2 * nf2], ah[mf], bl);
                    mma_bf16(acc[mf][2 * nf2], al[mf], bh);
                    mma_bf16(acc[mf][2 * nf2], ah[mf], bh);
                }
                bh[0] = h2;  bh[1] = h3;  bl[0] = lo2; bl[1] = lo3;
#pragma unroll
                for (int mf = 0; mf < 2; mf++) {
                    mma_bf16(acc[mf][2 * nf2 + 1], ah[mf], bl);
                    mma_bf16(acc[mf][2 * nf2 + 1], al[mf], bh);
                    mma_bf16(acc[mf][2 * nf2 + 1], ah[mf], bh);
                }
            }
        }
        __syncthreads();
    }

#pragma unroll
    for (int mf = 0; mf < 2; mf++) {
        const int row = m0 + wm * 32 + mf * 16 + g;
#pragma unroll
        for (int nf = 0; nf < 8; nf++) {
            const int col = n0 + wn * 64 + nf * 8 + 2 * lam;
            float b0 = bo[col];
            float b1 = bo[col + 1];
            float2 v0 = make_float2(acc[mf][nf][0] + b0, acc[mf][nf][1] + b1);
            float2 v1 = make_float2(acc[mf][nf][2] + b0, acc[mf][nf][3] + b1);
            *reinterpret_cast<float2*>(g_out + (size_t)row * EM + col) = v0;
            *reinterpret_cast<float2*>(g_out + (size_t)(row + 8) * EM + col) = v1;
        }
    }
}

// ---------------- kernel 5: residual + LayerNorm ----------------
__device__ __forceinline__ float block_sum_256(float val, float* sh)
{
    const int lane = threadIdx.x & 31;
    const int w    = threadIdx.x >> 5;
#pragma unroll
    for (int o = 16; o > 0; o >>= 1) val += __shfl_xor_sync(0xffffffffu, val, o);
    if (lane == 0) sh[w] = val;
    __syncthreads();
    if (w == 0) {
        float t = (lane < 8) ? sh[lane] : 0.f;
#pragma unroll
        for (int o = 4; o > 0; o >>= 1) t += __shfl_xor_sync(0xffffffffu, t, o);
        if (lane == 0) sh[0] = t;
    }
    __syncthreads();
    const float r = sh[0];
    __syncthreads();
    return r;
}

__global__ __launch_bounds__(256) void k_ln(const float* __restrict__ x,
                                            const float* __restrict__ gamma,
                                            const float* __restrict__ beta,
                                            float* __restrict__ out)
{
    __shared__ float sh[8];
    const int srow = blockIdx.x;
    const float* orow = g_out + (size_t)srow * EM;
    const float* xrow = x + (size_t)srow * EM;

    float v[4];
    float sum = 0.f;
#pragma unroll
    for (int i = 0; i < 4; i++) {
        const int c = threadIdx.x + i * 256;
        v[i] = orow[c] + xrow[c];
        sum += v[i];
    }
    const float mean = block_sum_256(sum, sh) * (1.f / EM);

    float var = 0.f;
#pragma unroll
    for (int i = 0; i < 4; i++) {
        const float d = v[i] - mean;
        var += d * d;
    }
    const float rstd = rsqrtf(block_sum_256(var, sh) * (1.f / EM) + 1e-5f);

#pragma unroll
    for (int i = 0; i < 4; i++) {
        const int c = threadIdx.x + i * 256;
        out[(size_t)srow * EM + c] = (v[i] - mean) * rstd * gamma[c] + beta[c];
    }
}

// ---------------- launch ----------------
extern "C" void kernel_launch(void* const* d_in, const int* in_sizes, int n_in,
                              void* d_out, int out_size)
{
    const float* x     = (const float*)d_in[0];
    const float* Wk    = (const float*)d_in[1];
    const float* Wq    = (const float*)d_in[2];
    const float* Wv    = (const float*)d_in[3];
    const float* hWk   = (const float*)d_in[4];
    const float* hbk   = (const float*)d_in[5];
    const float* hWv   = (const float*)d_in[6];
    const float* hbv   = (const float*)d_in[7];
    const float* hWq   = (const float*)d_in[8];
    const float* hbq   = (const float*)d_in[9];
    const float* Wo    = (const float*)d_in[10];
    const float* bo    = (const float*)d_in[11];
    const float* gamma = (const float*)d_in[12];
    const float* beta  = (const float*)d_in[13];
    float* out = (float*)d_out;

    const int attn_smem = 3 * STAGE_W * 4;
    cudaFuncSetAttribute(k_attn, cudaFuncAttributeMaxDynamicSharedMemorySize, attn_smem);
    const int oproj_smem = 2 * OSTAGE * 4;
    cudaFuncSetAttribute(k_outproj, cudaFuncAttributeMaxDynamicSharedMemorySize, oproj_smem);

    k_splitW<<<EM, 128>>>(Wo);
    k_proj<<<dim3(1, SQ / 32, 3), 128>>>(x, Wk, Wq, Wv);
    k_headlin<<<dim3(1, SQ / 64, 48), 128>>>(hWk, hbk, hWv, hbv, hWq, hbq);
    k_transpose<<<dim3(SQ / 32, DM / 32, NH), dim3(32, 8)>>>();
    k_attn<<<dim3(SQ / 128, NH), 256, attn_smem>>>();
    k_outproj<<<dim3(EM / 128, SQ / 128), 256, oproj_smem>>>(bo);
    k_ln<<<SQ, 256>>>(x, gamma, beta, out);
}